// round 1
// baseline (speedup 1.0000x reference)
#include <cuda_runtime.h>

#define Bb 8
#define Ll 512
#define Dd 256
#define Uu 32
#define TS 16   // s-rows per block in the fused kernel

// scratch: q (with bh folded) and k projections, [B*L, U]
__device__ float g_q[Bb * Ll * Uu];
__device__ float g_k[Bb * Ll * Uu];

__device__ __forceinline__ float fast_ex2(float x) {
    float y;
    asm("ex2.approx.f32 %0, %1;" : "=f"(y) : "f"(x));
    return y;
}
__device__ __forceinline__ float fast_rcp(float x) {
    float y;
    asm("rcp.approx.f32 %0, %1;" : "=f"(y) : "f"(x));
    return y;
}

// ---------------------------------------------------------------------------
// Kernel 1: q[row,u] = bh[u] + x[row,:]·Wt[:,u];  k[row,u] = x[row,:]·Wx[:,u]
// 8 rows per block, 256 threads: (u:32) x (q/k:2) x (row-pair:4)
// ---------------------------------------------------------------------------
__global__ __launch_bounds__(256) void qk_kernel(const float* __restrict__ x,
                                                 const float* __restrict__ Wt,
                                                 const float* __restrict__ Wx,
                                                 const float* __restrict__ bh) {
    __shared__ float xs[8 * Dd];
    const int row0 = blockIdx.x * 8;

    // load 8 x rows (2048 floats = 512 float4) cooperatively
    const float4* xg = (const float4*)(x + (size_t)row0 * Dd);
    float4* xs4 = (float4*)xs;
    xs4[threadIdx.x] = xg[threadIdx.x];
    xs4[threadIdx.x + 256] = xg[threadIdx.x + 256];
    __syncthreads();

    const int u = threadIdx.x & 31;
    const int which = (threadIdx.x >> 5) & 1;  // warp-uniform: 0 -> q, 1 -> k
    const int rp = threadIdx.x >> 6;           // 0..3
    const float* __restrict__ W = which ? Wx : Wt;

    float acc0 = which ? 0.f : bh[u];
    float acc1 = acc0;
    const float* xr0 = xs + rp * Dd;
    const float* xr1 = xs + (rp + 4) * Dd;

#pragma unroll 8
    for (int d = 0; d < Dd; d++) {
        float w = W[d * Uu + u];           // coalesced 128B per warp
        acc0 = fmaf(xr0[d], w, acc0);      // smem broadcast
        acc1 = fmaf(xr1[d], w, acc1);
    }

    float* dst = which ? g_k : g_q;
    dst[(row0 + rp) * Uu + u] = acc0;
    dst[(row0 + rp + 4) * Uu + u] = acc1;
}

// ---------------------------------------------------------------------------
// Kernel 2 (fused): per (b, 16-row s-tile)
//   A: alpha[s,t] = sum_u Wa_u * tanh(q[s,u] + k[t,u])
//   B: softmax over t (per s row)
//   C: c[s,:] = sum_t a[s,t] * x[b,t,:]
// ---------------------------------------------------------------------------
__global__ __launch_bounds__(512, 2) void attn_kernel(const float* __restrict__ x,
                                                      const float* __restrict__ Wa,
                                                      float* __restrict__ out) {
    __shared__ float sa[TS * Ll];   // 32 KB: alpha, then softmax weights
    __shared__ float sq[TS * Uu];   // 2 KB : q rows for this tile (bh folded)
    __shared__ float swa[Uu];       // Wa

    const int tid = threadIdx.x;
    const int b = blockIdx.x / (Ll / TS);
    const int s0 = (blockIdx.x % (Ll / TS)) * TS;

    if (tid < TS * Uu) sq[tid] = g_q[((size_t)b * Ll + s0) * Uu + tid];
    if (tid < Uu) swa[tid] = Wa[tid];
    __syncthreads();

    // -------- Phase A: thread `tid` owns key row t = tid (512 t's, 512 threads)
    {
        const int t = tid;
        float kk[32];
        const float4* kg = (const float4*)(g_k + ((size_t)b * Ll + t) * Uu);
#pragma unroll
        for (int i = 0; i < 8; i++) {
            float4 kv = kg[i];  // 8x LDG.128, warp reads 4KB contiguous
            kk[4 * i + 0] = kv.x; kk[4 * i + 1] = kv.y;
            kk[4 * i + 2] = kv.z; kk[4 * i + 3] = kv.w;
        }

        float sumwa = 0.f;
#pragma unroll
        for (int u = 0; u < Uu; u++) sumwa += swa[u];

        const float4* swa4 = (const float4*)swa;
        const float C2LOG2E = 2.8853900817779268f;  // 2*log2(e)

#pragma unroll
        for (int s = 0; s < TS; s++) {
            const float4* sq4 = (const float4*)(sq + s * Uu);
            float acc = 0.f;  // sum_u Wa_u * r_u,  r = 1/(1+e^{2z}),  tanh = 1-2r
#pragma unroll
            for (int i = 0; i < 8; i++) {
                float4 q4 = sq4[i];   // broadcast LDS
                float4 w4 = swa4[i];
                {
                    float e = fast_ex2((q4.x + kk[4 * i + 0]) * C2LOG2E);
                    acc = fmaf(w4.x, fast_rcp(e + 1.f), acc);
                }
                {
                    float e = fast_ex2((q4.y + kk[4 * i + 1]) * C2LOG2E);
                    acc = fmaf(w4.y, fast_rcp(e + 1.f), acc);
                }
                {
                    float e = fast_ex2((q4.z + kk[4 * i + 2]) * C2LOG2E);
                    acc = fmaf(w4.z, fast_rcp(e + 1.f), acc);
                }
                {
                    float e = fast_ex2((q4.w + kk[4 * i + 3]) * C2LOG2E);
                    acc = fmaf(w4.w, fast_rcp(e + 1.f), acc);
                }
            }
            sa[s * Ll + t] = fmaf(-2.f, acc, sumwa);  // coalesced STS
        }
    }
    __syncthreads();

    // -------- Phase B: warp w handles softmax of row s = w (16 warps, TS=16)
    {
        const int w = tid >> 5;
        const int lane = tid & 31;
        const float LOG2E = 1.4426950408889634f;

        float v[16];
        float m = -1e30f;
#pragma unroll
        for (int i = 0; i < 16; i++) {
            v[i] = sa[w * Ll + lane + 32 * i];
            m = fmaxf(m, v[i]);
        }
#pragma unroll
        for (int off = 16; off > 0; off >>= 1)
            m = fmaxf(m, __shfl_xor_sync(0xffffffffu, m, off));

        float ssum = 0.f;
#pragma unroll
        for (int i = 0; i < 16; i++) {
            v[i] = fast_ex2((v[i] - m) * LOG2E);
            ssum += v[i];
        }
#pragma unroll
        for (int off = 16; off > 0; off >>= 1)
            ssum += __shfl_xor_sync(0xffffffffu, ssum, off);

        const float inv = fast_rcp(ssum);
#pragma unroll
        for (int i = 0; i < 16; i++) sa[w * Ll + lane + 32 * i] = v[i] * inv;
    }
    __syncthreads();

    // -------- Phase C: thread owns column d = tid%256 and 8 s-rows (tid/256)
    {
        const int d = tid & 255;
        const int sg = tid >> 8;  // 0 or 1
        float acc[8] = {0.f, 0.f, 0.f, 0.f, 0.f, 0.f, 0.f, 0.f};
        const float* __restrict__ xb = x + (size_t)b * Ll * Dd;
        const float4* sa4 = (const float4*)sa;
        const int sbase = sg * 8;

        for (int t = 0; t < Ll; t += 4) {
            float x0 = xb[(t + 0) * Dd + d];  // 4 independent coalesced LDGs
            float x1 = xb[(t + 1) * Dd + d];
            float x2 = xb[(t + 2) * Dd + d];
            float x3 = xb[(t + 3) * Dd + d];
#pragma unroll
            for (int i = 0; i < 8; i++) {
                float4 av = sa4[((sbase + i) * Ll + t) >> 2];  // broadcast LDS.128
                acc[i] = fmaf(av.x, x0, acc[i]);
                acc[i] = fmaf(av.y, x1, acc[i]);
                acc[i] = fmaf(av.z, x2, acc[i]);
                acc[i] = fmaf(av.w, x3, acc[i]);
            }
        }

        float* ob = out + ((size_t)b * Ll + s0 + sbase) * Dd;
#pragma unroll
        for (int i = 0; i < 8; i++) ob[i * Dd + d] = acc[i];
    }
}

// ---------------------------------------------------------------------------
extern "C" void kernel_launch(void* const* d_in, const int* in_sizes, int n_in,
                              void* d_out, int out_size) {
    const float* x  = (const float*)d_in[0];
    const float* Wt = (const float*)d_in[1];
    const float* Wx = (const float*)d_in[2];
    const float* bh = (const float*)d_in[3];
    const float* Wa = (const float*)d_in[4];
    // d_in[5] = ba: uniform shift of alpha -> softmax-invariant, exactly droppable
    float* out = (float*)d_out;

    qk_kernel<<<Bb * Ll / 8, 256>>>(x, Wt, Wx, bh);
    attn_kernel<<<Bb * (Ll / TS), 512>>>(x, Wa, out);
}

// round 2
// speedup vs baseline: 1.1450x; 1.1450x over previous
#include <cuda_runtime.h>

#define Bb 8
#define Ll 512
#define Dd 256
#define Uu 32
#define TS 16      // s-rows per block in the fused kernel
#define PAD 20     // padded row stride (floats) of transposed weight tile

// scratch: Eq = exp2(C*(q+bh)) and Ek = exp2(C*k), [B*L, U], C = 2*log2(e)
__device__ float g_q[Bb * Ll * Uu];
__device__ float g_k[Bb * Ll * Uu];

__device__ __forceinline__ float fast_ex2(float x) {
    float y; asm("ex2.approx.f32 %0, %1;" : "=f"(y) : "f"(x)); return y;
}
__device__ __forceinline__ float fast_rcp(float x) {
    float y; asm("rcp.approx.f32 %0, %1;" : "=f"(y) : "f"(x)); return y;
}
__device__ __forceinline__ unsigned long long pack2(float lo, float hi) {
    unsigned long long r;
    asm("mov.b64 %0, {%1, %2};" : "=l"(r) : "f"(lo), "f"(hi));
    return r;
}
__device__ __forceinline__ void unpack2(float& lo, float& hi, unsigned long long v) {
    asm("mov.b64 {%0, %1}, %2;" : "=f"(lo), "=f"(hi) : "l"(v));
}
__device__ __forceinline__ void fma2(unsigned long long& d, unsigned long long a,
                                     unsigned long long b) {
    asm("fma.rn.f32x2 %0, %1, %2, %0;" : "+l"(d) : "l"(a), "l"(b));
}

// ---------------------------------------------------------------------------
// Kernel 1: Eq[row,u] = exp2(C*(bh[u] + x[row,:]·Wt[:,u]))
//           Ek[row,u] = exp2(C*(x[row,:]·Wx[:,u]))
// 8 rows per block, 256 threads: (u:32) x (q/k:2) x (row-pair:4)
// ---------------------------------------------------------------------------
__global__ __launch_bounds__(256) void qk_kernel(const float* __restrict__ x,
                                                 const float* __restrict__ Wt,
                                                 const float* __restrict__ Wx,
                                                 const float* __restrict__ bh) {
    __shared__ float xs[8 * Dd];
    const int row0 = blockIdx.x * 8;

    const float4* xg = (const float4*)(x + (size_t)row0 * Dd);
    float4* xs4 = (float4*)xs;
    xs4[threadIdx.x] = xg[threadIdx.x];
    xs4[threadIdx.x + 256] = xg[threadIdx.x + 256];
    __syncthreads();

    const int u = threadIdx.x & 31;
    const int which = (threadIdx.x >> 5) & 1;  // warp-uniform: 0 -> q, 1 -> k
    const int rp = threadIdx.x >> 6;           // 0..3
    const float* __restrict__ W = which ? Wx : Wt;

    float acc0 = which ? 0.f : bh[u];
    float acc1 = acc0;
    const float* xr0 = xs + rp * Dd;
    const float* xr1 = xs + (rp + 4) * Dd;

#pragma unroll 8
    for (int d = 0; d < Dd; d++) {
        float w = W[d * Uu + u];
        acc0 = fmaf(xr0[d], w, acc0);
        acc1 = fmaf(xr1[d], w, acc1);
    }

    const float C2LOG2E = 2.8853900817779268f;  // 2*log2(e)
    float* dst = which ? g_k : g_q;
    dst[(row0 + rp) * Uu + u] = fast_ex2(C2LOG2E * acc0);
    dst[(row0 + rp + 4) * Uu + u] = fast_ex2(C2LOG2E * acc1);
}

// ---------------------------------------------------------------------------
// Kernel 2 (fused): per (b, 16-row s-tile)
//   A: alpha[s,t] = sumWa - 2*sum_u Wa_u / (1 + Eq[s,u]*Ek[t,u])
//   B: softmax over t (per s row)
//   C: c[s,:] = sum_t a[s,t] * x[b,t,:]   (packed f32x2 FFMA)
// Weight tile stored transposed sa_t[t][s] with padded stride PAD.
// ---------------------------------------------------------------------------
__global__ __launch_bounds__(512, 2) void attn_kernel(const float* __restrict__ x,
                                                      const float* __restrict__ Wa,
                                                      float* __restrict__ out) {
    __shared__ float sa[Ll * PAD];  // 40 KB: alpha / softmax weights, [t][s]
    __shared__ float sq[TS * Uu];   // 2 KB : Eq rows for this tile
    __shared__ float swa[Uu];       // Wa

    const int tid = threadIdx.x;
    const int b = blockIdx.x / (Ll / TS);
    const int s0 = (blockIdx.x % (Ll / TS)) * TS;

    if (tid < TS * Uu) sq[tid] = g_q[((size_t)b * Ll + s0) * Uu + tid];
    if (tid < Uu) swa[tid] = Wa[tid];
    __syncthreads();

    // -------- Phase A: thread `tid` owns key row t = tid
    {
        const int t = tid;
        float kk[32];
        const float4* kg = (const float4*)(g_k + ((size_t)b * Ll + t) * Uu);
#pragma unroll
        for (int i = 0; i < 8; i++) {
            float4 kv = kg[i];
            kk[4 * i + 0] = kv.x; kk[4 * i + 1] = kv.y;
            kk[4 * i + 2] = kv.z; kk[4 * i + 3] = kv.w;
        }

        float sumwa = 0.f;
#pragma unroll
        for (int u = 0; u < Uu; u++) sumwa += swa[u];

        const float4* swa4 = (const float4*)swa;

#pragma unroll
        for (int s = 0; s < TS; s++) {
            const float4* eq4 = (const float4*)(sq + s * Uu);
            float acc0 = 0.f, acc1 = 0.f;
#pragma unroll
            for (int i = 0; i < 8; i++) {
                float4 q4 = eq4[i];   // broadcast LDS
                float4 w4 = swa4[i];
                acc0 = fmaf(w4.x, fast_rcp(fmaf(kk[4 * i + 0], q4.x, 1.f)), acc0);
                acc1 = fmaf(w4.y, fast_rcp(fmaf(kk[4 * i + 1], q4.y, 1.f)), acc1);
                acc0 = fmaf(w4.z, fast_rcp(fmaf(kk[4 * i + 2], q4.z, 1.f)), acc0);
                acc1 = fmaf(w4.w, fast_rcp(fmaf(kk[4 * i + 3], q4.w, 1.f)), acc1);
            }
            sa[t * PAD + s] = fmaf(-2.f, acc0 + acc1, sumwa);
        }
    }
    __syncthreads();

    // -------- Phase B: warp w handles softmax of row s = w (16 warps)
    {
        const int w = tid >> 5;
        const int lane = tid & 31;
        const float LOG2E = 1.4426950408889634f;

        float v[16];
        float m = -1e30f;
#pragma unroll
        for (int i = 0; i < 16; i++) {
            v[i] = sa[(lane + 32 * i) * PAD + w];
            m = fmaxf(m, v[i]);
        }
#pragma unroll
        for (int off = 16; off > 0; off >>= 1)
            m = fmaxf(m, __shfl_xor_sync(0xffffffffu, m, off));

        float ssum = 0.f;
#pragma unroll
        for (int i = 0; i < 16; i++) {
            v[i] = fast_ex2((v[i] - m) * LOG2E);
            ssum += v[i];
        }
#pragma unroll
        for (int off = 16; off > 0; off >>= 1)
            ssum += __shfl_xor_sync(0xffffffffu, ssum, off);

        const float inv = fast_rcp(ssum);
#pragma unroll
        for (int i = 0; i < 16; i++) sa[(lane + 32 * i) * PAD + w] = v[i] * inv;
    }
    __syncthreads();

    // -------- Phase C: thread owns column d = tid%256 and 8 s-rows (packed as
    // 4 f32x2 accumulators over consecutive-s pairs)
    {
        const int d = tid & 255;
        const int sbase = (tid >> 8) * 8;  // 0 or 8
        unsigned long long acc0 = 0ull, acc1 = 0ull, acc2 = 0ull, acc3 = 0ull;
        const float* __restrict__ xb = x + (size_t)b * Ll * Dd + d;
        const float* sp = sa + sbase;

        for (int t = 0; t < Ll; t += 4) {
            float x0 = xb[(t + 0) * Dd];
            float x1 = xb[(t + 1) * Dd];
            float x2 = xb[(t + 2) * Dd];
            float x3 = xb[(t + 3) * Dd];

            ulonglong2 a0 = *(const ulonglong2*)(sp + (t + 0) * PAD);      // s..s+3
            ulonglong2 b0 = *(const ulonglong2*)(sp + (t + 0) * PAD + 4);  // s+4..s+7
            ulonglong2 a1 = *(const ulonglong2*)(sp + (t + 1) * PAD);
            ulonglong2 b1 = *(const ulonglong2*)(sp + (t + 1) * PAD + 4);
            ulonglong2 a2 = *(const ulonglong2*)(sp + (t + 2) * PAD);
            ulonglong2 b2 = *(const ulonglong2*)(sp + (t + 2) * PAD + 4);
            ulonglong2 a3 = *(const ulonglong2*)(sp + (t + 3) * PAD);
            ulonglong2 b3 = *(const ulonglong2*)(sp + (t + 3) * PAD + 4);

            unsigned long long xx0 = pack2(x0, x0);
            unsigned long long xx1 = pack2(x1, x1);
            unsigned long long xx2 = pack2(x2, x2);
            unsigned long long xx3 = pack2(x3, x3);

            fma2(acc0, a0.x, xx0); fma2(acc1, a0.y, xx0);
            fma2(acc2, b0.x, xx0); fma2(acc3, b0.y, xx0);
            fma2(acc0, a1.x, xx1); fma2(acc1, a1.y, xx1);
            fma2(acc2, b1.x, xx1); fma2(acc3, b1.y, xx1);
            fma2(acc0, a2.x, xx2); fma2(acc1, a2.y, xx2);
            fma2(acc2, b2.x, xx2); fma2(acc3, b2.y, xx2);
            fma2(acc0, a3.x, xx3); fma2(acc1, a3.y, xx3);
            fma2(acc2, b3.x, xx3); fma2(acc3, b3.y, xx3);
        }

        float* ob = out + ((size_t)b * Ll + s0 + sbase) * Dd + d;
        float lo, hi;
        unpack2(lo, hi, acc0); ob[0 * Dd] = lo; ob[1 * Dd] = hi;
        unpack2(lo, hi, acc1); ob[2 * Dd] = lo; ob[3 * Dd] = hi;
        unpack2(lo, hi, acc2); ob[4 * Dd] = lo; ob[5 * Dd] = hi;
        unpack2(lo, hi, acc3); ob[6 * Dd] = lo; ob[7 * Dd] = hi;
    }
}

// ---------------------------------------------------------------------------
extern "C" void kernel_launch(void* const* d_in, const int* in_sizes, int n_in,
                              void* d_out, int out_size) {
    const float* x  = (const float*)d_in[0];
    const float* Wt = (const float*)d_in[1];
    const float* Wx = (const float*)d_in[2];
    const float* bh = (const float*)d_in[3];
    const float* Wa = (const float*)d_in[4];
    // d_in[5] = ba: uniform shift of alpha -> softmax-invariant, exactly droppable
    float* out = (float*)d_out;

    qk_kernel<<<Bb * Ll / 8, 256>>>(x, Wt, Wx, bh);
    attn_kernel<<<Bb * (Ll / TS), 512>>>(x, Wa, out);
}